// round 1
// baseline (speedup 1.0000x reference)
#include <cuda_runtime.h>

#define IN      6
#define H       64
#define BB      4096
#define TT      512
#define NOUT    3
#define BTILE   28
#define NTHREADS 448        // 64 units * 7 batch-groups
#define NGRID   147         // ceil(4096/28)

// ---- shared memory layout (in floats) ----
#define OFF_W1P   0                         // [k=128][j=64][g=4]  (k<64: Wih1, k>=64: Whh1)
#define OFF_W0P   (OFF_W1P  + 128*64*4)     // [k=64][j=64][g=4]   Whh0
#define OFF_WX0P  (OFF_W0P  + 64*64*4)      // [k=6][j=64][g=4]    Wih0
#define OFF_BA    (OFF_WX0P + 6*64*4)       // [j=64][g=4]         bih0+bhh0
#define OFF_BB    (OFF_BA   + 256)          // [j=64][g=4]         bih1+bhh1
#define OFF_HA    (OFF_BB   + 256)          // [28][64]
#define OFF_HB    (OFF_HA   + BTILE*H)      // [28][64]
#define OFF_WFC   (OFF_HB   + BTILE*H)      // [3][64]
#define OFF_BFC   (OFF_WFC  + NOUT*H)       // 4 (padded)
#define OFF_XS    (OFF_BFC  + 4)            // 2 * [28][6]
#define SMEM_FLOATS (OFF_XS + 2*BTILE*IN)

__device__ __forceinline__ float fexp2_(float x) {
    float y; asm("ex2.approx.f32 %0, %1;" : "=f"(y) : "f"(x)); return y;
}
__device__ __forceinline__ float frcp_(float x) {
    float y; asm("rcp.approx.f32 %0, %1;" : "=f"(y) : "f"(x)); return y;
}
__device__ __forceinline__ float sigm_(float x) {
    // 1 / (1 + 2^(-x*log2(e)))
    float e = fexp2_(-1.4426950408889634f * x);
    return frcp_(1.0f + e);
}
__device__ __forceinline__ float tanh_(float x) {
    // 2*sigmoid(2x) - 1
    float e = fexp2_(-2.8853900817779268f * x);
    return fmaf(2.0f, frcp_(1.0f + e), -1.0f);
}

// acc (float4 over gates i,f,g,o) += u.{x,y,z,w} * w{0..3}
#define FMA16(a, u) do {                                                                             \
    a.x = fmaf(u.x, w0.x, a.x); a.y = fmaf(u.x, w0.y, a.y); a.z = fmaf(u.x, w0.z, a.z); a.w = fmaf(u.x, w0.w, a.w); \
    a.x = fmaf(u.y, w1.x, a.x); a.y = fmaf(u.y, w1.y, a.y); a.z = fmaf(u.y, w1.z, a.z); a.w = fmaf(u.y, w1.w, a.w); \
    a.x = fmaf(u.z, w2.x, a.x); a.y = fmaf(u.z, w2.y, a.y); a.z = fmaf(u.z, w2.z, a.z); a.w = fmaf(u.z, w2.w, a.w); \
    a.x = fmaf(u.w, w3.x, a.x); a.y = fmaf(u.w, w3.y, a.y); a.z = fmaf(u.w, w3.z, a.z); a.w = fmaf(u.w, w3.w, a.w); \
} while (0)

// 64-deep K block: accumulate 4 batches x 4 gates for unit j
__device__ __forceinline__ void gemm_block(
    float4& a0, float4& a1, float4& a2, float4& a3,
    const float4* __restrict__ Wp,   // [k][64] float4 (gate quads)
    const float4* __restrict__ u4,   // [b][16] float4 (h as 16 float4 per batch)
    int j, int bl0)
{
#pragma unroll 4
    for (int k4 = 0; k4 < 16; ++k4) {
        float4 w0 = Wp[(k4 * 4 + 0) * 64 + j];
        float4 w1 = Wp[(k4 * 4 + 1) * 64 + j];
        float4 w2 = Wp[(k4 * 4 + 2) * 64 + j];
        float4 w3 = Wp[(k4 * 4 + 3) * 64 + j];
        float4 u0 = u4[(bl0 + 0) * 16 + k4];
        float4 u1 = u4[(bl0 + 1) * 16 + k4];
        float4 u2 = u4[(bl0 + 2) * 16 + k4];
        float4 u3 = u4[(bl0 + 3) * 16 + k4];
        FMA16(a0, u0); FMA16(a1, u1); FMA16(a2, u2); FMA16(a3, u3);
    }
}

__device__ __forceinline__ float cellact(float4 a, float& c) {
    float ig = sigm_(a.x);
    float fg = sigm_(a.y);
    float gg = tanh_(a.z);
    float og = sigm_(a.w);
    c = fmaf(fg, c, ig * gg);
    return og * tanh_(c);
}

__global__ void __launch_bounds__(NTHREADS, 1)
lstm2_kernel(const float* __restrict__ x,
             const float* __restrict__ Wih0, const float* __restrict__ Whh0,
             const float* __restrict__ bih0, const float* __restrict__ bhh0,
             const float* __restrict__ Wih1, const float* __restrict__ Whh1,
             const float* __restrict__ bih1, const float* __restrict__ bhh1,
             const float* __restrict__ Wfc,  const float* __restrict__ bfc,
             float* __restrict__ out)
{
    extern __shared__ float sm[];
    const int tid = threadIdx.x;
    const int j   = tid & 63;        // hidden unit
    const int bg  = tid >> 6;        // batch group 0..6
    const int bl0 = bg * 4;          // first local batch of this thread
    const int b0  = blockIdx.x * BTILE;

    // ---- pack weights into SMEM (gate-quad layout) ----
    for (int idx = tid; idx < 128 * 64 * 4; idx += NTHREADS) {
        int g = idx & 3, jj = (idx >> 2) & 63, k = idx >> 8;
        sm[OFF_W1P + idx] = (k < 64) ? Wih1[(g * 64 + jj) * 64 + k]
                                     : Whh1[(g * 64 + jj) * 64 + (k - 64)];
    }
    for (int idx = tid; idx < 64 * 64 * 4; idx += NTHREADS) {
        int g = idx & 3, jj = (idx >> 2) & 63, k = idx >> 8;
        sm[OFF_W0P + idx] = Whh0[(g * 64 + jj) * 64 + k];
    }
    for (int idx = tid; idx < 6 * 64 * 4; idx += NTHREADS) {
        int g = idx & 3, jj = (idx >> 2) & 63, k = idx >> 8;
        sm[OFF_WX0P + idx] = Wih0[(g * 64 + jj) * 6 + k];
    }
    for (int idx = tid; idx < 256; idx += NTHREADS) {
        int g = idx & 3, jj = idx >> 2;
        sm[OFF_BA + idx] = bih0[g * 64 + jj] + bhh0[g * 64 + jj];
        sm[OFF_BB + idx] = bih1[g * 64 + jj] + bhh1[g * 64 + jj];
    }
    for (int idx = tid; idx < NOUT * H; idx += NTHREADS) sm[OFF_WFC + idx] = Wfc[idx];
    if (tid < NOUT) sm[OFF_BFC + tid] = bfc[tid];
    if (tid == NOUT) sm[OFF_BFC + 3] = 0.0f;
    for (int idx = tid; idx < BTILE * H; idx += NTHREADS) {
        sm[OFF_HA + idx] = 0.0f;
        sm[OFF_HB + idx] = 0.0f;
    }

    // x prefetch mapping (threads 0..167)
    const int xb = tid / IN;
    const int xf = tid - xb * IN;
    const bool xthr  = (tid < BTILE * IN);
    const bool xload = xthr && (b0 + xb < BB);
    if (xthr) sm[OFF_XS + tid] = xload ? x[((size_t)(b0 + xb) * TT + 0) * IN + xf] : 0.0f;

    __syncthreads();

    const float4* W1p4  = (const float4*)(sm + OFF_W1P);
    const float4* W0p4  = (const float4*)(sm + OFF_W0P);
    const float4* Wx0p4 = (const float4*)(sm + OFF_WX0P);
    const float4  biasA = ((const float4*)(sm + OFF_BA))[j];
    const float4  biasB = ((const float4*)(sm + OFF_BB))[j];
    float* hA = sm + OFF_HA;
    float* hB = sm + OFF_HB;
    const float4* hA4 = (const float4*)hA;
    const float4* hB4 = (const float4*)hB;

    float cA0 = 0.f, cA1 = 0.f, cA2 = 0.f, cA3 = 0.f;
    float cB0 = 0.f, cB1 = 0.f, cB2 = 0.f, cB3 = 0.f;

    for (int t = 0; t < TT; ++t) {
        float* xcur = sm + OFF_XS + (t & 1) * (BTILE * IN);
        float* xnxt = sm + OFF_XS + ((t + 1) & 1) * (BTILE * IN);

        // prefetch next timestep's x into a register (latency hidden under GEMMs)
        float xpre = 0.0f;
        if (t + 1 < TT && xload)
            xpre = x[((size_t)(b0 + xb) * TT + (t + 1)) * IN + xf];

        // ---------- layer 0 ----------
        float4 a0 = biasA, a1 = biasA, a2 = biasA, a3 = biasA;
        // input contribution (k = 0..5)
#pragma unroll
        for (int k = 0; k < IN; ++k) {
            float4 w0 = Wx0p4[k * 64 + j];
            float x0 = xcur[(bl0 + 0) * IN + k];
            float x1 = xcur[(bl0 + 1) * IN + k];
            float x2 = xcur[(bl0 + 2) * IN + k];
            float x3 = xcur[(bl0 + 3) * IN + k];
            a0.x = fmaf(x0, w0.x, a0.x); a0.y = fmaf(x0, w0.y, a0.y); a0.z = fmaf(x0, w0.z, a0.z); a0.w = fmaf(x0, w0.w, a0.w);
            a1.x = fmaf(x1, w0.x, a1.x); a1.y = fmaf(x1, w0.y, a1.y); a1.z = fmaf(x1, w0.z, a1.z); a1.w = fmaf(x1, w0.w, a1.w);
            a2.x = fmaf(x2, w0.x, a2.x); a2.y = fmaf(x2, w0.y, a2.y); a2.z = fmaf(x2, w0.z, a2.z); a2.w = fmaf(x2, w0.w, a2.w);
            a3.x = fmaf(x3, w0.x, a3.x); a3.y = fmaf(x3, w0.y, a3.y); a3.z = fmaf(x3, w0.z, a3.z); a3.w = fmaf(x3, w0.w, a3.w);
        }
        // recurrent contribution (hA of t-1)
        gemm_block(a0, a1, a2, a3, W0p4, hA4, j, bl0);

        float n0 = cellact(a0, cA0);
        float n1 = cellact(a1, cA1);
        float n2 = cellact(a2, cA2);
        float n3 = cellact(a3, cA3);

        __syncthreads();                      // everyone done reading old hA
        hA[(bl0 + 0) * H + j] = n0;
        hA[(bl0 + 1) * H + j] = n1;
        hA[(bl0 + 2) * H + j] = n2;
        hA[(bl0 + 3) * H + j] = n3;
        __syncthreads();                      // new hA visible

        // ---------- layer 1 ----------
        a0 = biasB; a1 = biasB; a2 = biasB; a3 = biasB;
        gemm_block(a0, a1, a2, a3, W1p4,           hA4, j, bl0);   // Wih1 @ hA(t)
        gemm_block(a0, a1, a2, a3, W1p4 + 64 * 64, hB4, j, bl0);   // Whh1 @ hB(t-1)

        n0 = cellact(a0, cB0);
        n1 = cellact(a1, cB1);
        n2 = cellact(a2, cB2);
        n3 = cellact(a3, cB3);

        __syncthreads();                      // everyone done reading old hB
        hB[(bl0 + 0) * H + j] = n0;
        hB[(bl0 + 1) * H + j] = n1;
        hB[(bl0 + 2) * H + j] = n2;
        hB[(bl0 + 3) * H + j] = n3;
        if (t + 1 < TT && xthr) xnxt[tid] = xpre;
        __syncthreads();                      // hB + next x ready
    }

    // ---------- final FC: out = hB(T-1) @ Wfc^T + bfc ----------
    if (j < NOUT) {
#pragma unroll
        for (int ib = 0; ib < 4; ++ib) {
            int b = b0 + bl0 + ib;
            if (b < BB) {
                float acc = sm[OFF_BFC + j];
                const float* wr = sm + OFF_WFC + j * H;
                const float* hr = hB + (bl0 + ib) * H;
#pragma unroll
                for (int k = 0; k < H; ++k) acc = fmaf(hr[k], wr[k], acc);
                out[b * NOUT + j] = acc;
            }
        }
    }
}

extern "C" void kernel_launch(void* const* d_in, const int* in_sizes, int n_in,
                              void* d_out, int out_size)
{
    const float* x    = (const float*)d_in[0];
    const float* Wih0 = (const float*)d_in[1];
    const float* Whh0 = (const float*)d_in[2];
    const float* bih0 = (const float*)d_in[3];
    const float* bhh0 = (const float*)d_in[4];
    const float* Wih1 = (const float*)d_in[5];
    const float* Whh1 = (const float*)d_in[6];
    const float* bih1 = (const float*)d_in[7];
    const float* bhh1 = (const float*)d_in[8];
    const float* Wfc  = (const float*)d_in[9];
    const float* bfc  = (const float*)d_in[10];
    float* out = (float*)d_out;

    const size_t smem = (size_t)SMEM_FLOATS * sizeof(float);  // ~221 KB
    cudaFuncSetAttribute(lstm2_kernel,
                         cudaFuncAttributeMaxDynamicSharedMemorySize, (int)smem);
    lstm2_kernel<<<NGRID, NTHREADS, smem>>>(x, Wih0, Whh0, bih0, bhh0,
                                            Wih1, Whh1, bih1, bhh1,
                                            Wfc, bfc, out);
}